// round 15
// baseline (speedup 1.0000x reference)
#include <cuda_runtime.h>
#include <cuda_fp16.h>
#include <cstdint>

#define PV   113
#define PVP  128
#define DIM  128
#define NH   4
#define DHD  32
#define HID  512
#define NCOMBO 226
#define NCOMBOP 228
#define NPAIR (PV*PV)      // 12769
#define NTOK  (NPAIR*2)    // 25538
#define PPB   32           // pairs per CTA (64 rows)
#define KCH   64
#define NCHUNK 8
#define GEMM_GRID ((NPAIR + PPB - 1)/PPB)   // 400

// ---------------- device scratch (zero-initialized) ----------------
__device__ __align__(16) float g_vv [256*DIM];
__device__ __align__(16) float g_OW1[DIM*HID];
__device__ __align__(16) float g_OU [DIM*PV];
__device__ __align__(16) float g_qk [2*NCOMBO*DIM + 4*DIM];
__device__ __align__(16) float g_EU [NCOMBOP*PVP];              // fp32 (b2 folded)
__device__ __align__(16) __half g_AUh[NCOMBOP*NH*PVP];          // fp16
__device__ __align__(16) __half g_Acz[NCHUNK*NCOMBOP*5*64];     // [chunk][combo][slot0=E,1..4=A][64]
__device__ __align__(16) __half g_Bh[HID*DIM];                  // [k][n] W2U fp16
__device__ __align__(16) float g_table[(size_t)NTOK*PV];

// ---------------- helpers ----------------
__device__ __forceinline__ uint32_t smem_u32(const void* p){
    uint32_t a;
    asm("{ .reg .u64 t; cvta.to.shared.u64 t, %1; cvt.u32.u64 %0, t; }" : "=r"(a) : "l"(p));
    return a;
}
__device__ __forceinline__ void cpa16(uint32_t dst, const void* src){
    asm volatile("cp.async.cg.shared.global [%0], [%1], 16;" :: "r"(dst), "l"(src));
}
__device__ __forceinline__ void cpa_commit(){ asm volatile("cp.async.commit_group;"); }
__device__ __forceinline__ void cpa_wait0(){ asm volatile("cp.async.wait_group 0;"); }
__device__ __forceinline__ void ldsm4(uint32_t* r, uint32_t a){
    asm volatile("ldmatrix.sync.aligned.m8n8.x4.shared.b16 {%0,%1,%2,%3}, [%4];"
        : "=r"(r[0]),"=r"(r[1]),"=r"(r[2]),"=r"(r[3]) : "r"(a));
}
__device__ __forceinline__ void ldsm4t(uint32_t* r, uint32_t a){
    asm volatile("ldmatrix.sync.aligned.m8n8.x4.trans.shared.b16 {%0,%1,%2,%3}, [%4];"
        : "=r"(r[0]),"=r"(r[1]),"=r"(r[2]),"=r"(r[3]) : "r"(a));
}
__device__ __forceinline__ void mma16816(float* c, const uint32_t* a, uint32_t b0, uint32_t b1){
    asm volatile("mma.sync.aligned.m16n8k16.row.col.f32.f16.f16.f32 "
        "{%0,%1,%2,%3}, {%4,%5,%6,%7}, {%8,%9}, {%0,%1,%2,%3};"
        : "+f"(c[0]),"+f"(c[1]),"+f"(c[2]),"+f"(c[3])
        : "r"(a[0]),"r"(a[1]),"r"(a[2]),"r"(a[3]), "r"(b0),"r"(b1));
}
__device__ __forceinline__ int permA(int m){ int t = m & 7; return (t>>1) | ((t&1)<<2); }

// ---------------- tiled 64x64 GEMM core (K multiple of 32) ----------------
template<class LA, class LB, class LC>
__device__ __forceinline__ void tg64(float (&As)[32][68], float (&Bs)[32][68],
                                     int K, LA la, LB lb, LC lc){
    const int tid = threadIdx.x;
    const int tx = tid & 15, ty = tid >> 4;
    float acc[4][4] = {};
    for (int k0 = 0; k0 < K; k0 += 32){
        {
            int am = tid >> 2, ak = (tid & 3) * 8;
            #pragma unroll
            for (int u=0;u<8;u++) As[ak+u][am] = la(am, k0+ak+u);
        }
        {
            int bk = tid >> 3, bn = (tid & 7) * 8;
            #pragma unroll
            for (int u=0;u<8;u++) Bs[bk][bn+u] = lb(k0+bk, bn+u);
        }
        __syncthreads();
        #pragma unroll
        for (int k=0;k<32;k++){
            float4 a4 = *(const float4*)&As[k][ty*4];
            float4 b4 = *(const float4*)&Bs[k][tx*4];
            float av[4] = {a4.x,a4.y,a4.z,a4.w};
            float bv[4] = {b4.x,b4.y,b4.z,b4.w};
            #pragma unroll
            for (int i=0;i<4;i++)
                #pragma unroll
                for (int j=0;j<4;j++) acc[i][j] += av[i]*bv[j];
        }
        __syncthreads();
    }
    #pragma unroll
    for (int i=0;i<4;i++)
        #pragma unroll
        for (int j=0;j<4;j++) lc(ty*4+i, tx*4+j, acc[i][j]);
}

// ---------------- P1: weight folds + E-side GEMMs ----------------
__global__ void __launch_bounds__(256) kP1(
    const float* __restrict__ tok_emb, const float* __restrict__ pos_emb,
    const float* __restrict__ WO, const float* __restrict__ W1,
    const float* __restrict__ WQ, const float* __restrict__ WK,
    const float* __restrict__ WV, const float* __restrict__ b1,
    const float* __restrict__ W2, const float* __restrict__ WU,
    const float* __restrict__ b2){
    __shared__ float As[32][68], Bs[32][68];
    int b = blockIdx.x;
    if (b < 16){                                  // OW1 = WO @ W1
        int l = b; int m0 = (l>>3)*64, n0 = (l&7)*64;
        tg64(As, Bs, 128,
            [&](int m,int k){ return WO[(m0+m)*DIM + k]; },
            [&](int k,int n){ return W1[k*HID + n0+n]; },
            [&](int m,int n,float v){ g_OW1[(m0+m)*HID + n0+n] = v; });
    } else if (b < 20){                           // OU = WO @ WU^T
        int l = b-16; int m0 = (l>>1)*64, n0 = (l&1)*64;
        tg64(As, Bs, 128,
            [&](int m,int k){ return WO[(m0+m)*DIM + k]; },
            [&](int k,int n){ int nn=n0+n; return nn<PV ? WU[nn*DIM + k] : 0.f; },
            [&](int m,int n,float v){ int nn=n0+n; if (nn<PV) g_OU[(m0+m)*PV + nn] = v; });
    } else if (b < 36){                           // Bh = fp16(W2 @ WU^T)
        int l = b-20; int m0 = (l>>1)*64, n0 = (l&1)*64;
        tg64(As, Bs, 128,
            [&](int m,int k){ return W2[(m0+m)*DIM + k]; },
            [&](int k,int n){ int nn=n0+n; return nn<PV ? WU[nn*DIM + k] : 0.f; },
            [&](int m,int n,float v){ g_Bh[(m0+m)*DIM + n0+n] = __float2half_rn(v); });
    } else if (b < 52){                           // q/k = E @ WQ/WK
        int l = b-36; int sel = l >> 3; l &= 7;
        int m0 = (l>>1)*64, n0 = (l&1)*64;
        const float* W = sel ? WK : WQ;
        tg64(As, Bs, 128,
            [&](int m,int k){ int c=m0+m; return c<NCOMBO ?
                tok_emb[(c>>1)*DIM + k] + pos_emb[(c&1)*DIM + k] : 0.f; },
            [&](int k,int n){ int nn=n0+n; return W[(nn>>5)*(DIM*DHD) + k*DHD + (nn&31)]; },
            [&](int m,int n,float v){ int c=m0+m; if (c<NCOMBO)
                g_qk[(sel*NCOMBO + c)*DIM + n0+n] = v; });
    } else if (b < 60){                           // vv = E @ WV
        int l = b-52; int m0 = (l>>1)*64, n0 = (l&1)*64;
        tg64(As, Bs, 128,
            [&](int m,int k){ int c=m0+m; return c<NCOMBO ?
                tok_emb[(c>>1)*DIM + k] + pos_emb[(c&1)*DIM + k] : 0.f; },
            [&](int k,int n){ int nn=n0+n; return WV[(nn>>5)*(DIM*DHD) + k*DHD + (nn&31)]; },
            [&](int m,int n,float v){ g_vv[(m0+m)*DIM + n0+n] = v; });
    } else if (b < 92){                           // EW1 = E @ W1 + b1 -> Acz slot 0
        int l = b-60; int m0 = (l>>3)*64, n0 = (l&7)*64;
        tg64(As, Bs, 128,
            [&](int m,int k){ int c=m0+m; return c<NCOMBO ?
                tok_emb[(c>>1)*DIM + k] + pos_emb[(c&1)*DIM + k] : 0.f; },
            [&](int k,int n){ return W1[k*HID + n0+n]; },
            [&](int m,int n,float v){ int c=m0+m, j=n0+n; if (c<NCOMBO)
                g_Acz[(((j>>6)*NCOMBOP + c)*5 + 0)*64 + (j&63)] = __float2half_rn(v + b1[j]); });
    } else {                                      // EU = (E + b2) @ WU^T (fp32)
        int l = b-92; int m0 = (l>>1)*64, n0 = (l&1)*64;
        tg64(As, Bs, 128,
            [&](int m,int k){ int c=m0+m; return (c<NCOMBO ?
                tok_emb[(c>>1)*DIM + k] + pos_emb[(c&1)*DIM + k] : 0.f) + b2[k]; },
            [&](int k,int n){ int nn=n0+n; return nn<PV ? WU[nn*DIM + k] : 0.f; },
            [&](int m,int n,float v){ int c=m0+m; if (c<NCOMBO)
                g_EU[c*PVP + n0+n] = v; });
    }
}

// ---------------- P2: vv-dependent folds (merged) ----------------
__global__ void __launch_bounds__(256) kP2(){
    __shared__ float As[32][68], Bs[32][68];
    int b = blockIdx.x;
    if (b < 128){                                 // AW1[h] = vv_h @ OW1_h -> Acz slots 1..4
        int h = b >> 5; int l = b & 31;
        int m0 = (l>>3)*64, n0 = (l&7)*64;
        tg64(As, Bs, 32,
            [&](int m,int k){ return g_vv[(m0+m)*DIM + h*DHD + k]; },
            [&](int k,int n){ return g_OW1[(h*DHD + k)*HID + n0+n]; },
            [&](int m,int n,float v){ int c=m0+m, j=n0+n; if (c<NCOMBO)
                g_Acz[(((j>>6)*NCOMBOP + c)*5 + 1 + h)*64 + (j&63)] = __float2half_rn(v); });
    } else {                                      // AU[h] = vv_h @ OU_h (fp16)
        int l = b-128; int h = l >> 3; int t = l & 7;
        int m0 = (t>>1)*64, n0 = (t&1)*64;
        tg64(As, Bs, 32,
            [&](int m,int k){ return g_vv[(m0+m)*DIM + h*DHD + k]; },
            [&](int k,int n){ int nn=n0+n; return nn<PV ? g_OU[(h*DHD + k)*PV + nn] : 0.f; },
            [&](int m,int n,float v){ int c=m0+m, nn=n0+n; if (c<NCOMBO && nn<PV)
                g_AUh[(c*NH + h)*PVP + nn] = __float2half_rn(v); });
    }
}

// ---------------- kFB9: no-ACZ-staging fused kernel, 4 CTAs/SM ----------------
#define SM_PAT   0        // 2048
#define SM_ATILE 2048     // 8192
#define SM_B     10240    // 2*16384
#define SMEM_TOT 43008

__global__ void __launch_bounds__(256, 4) kFB9(){
    extern __shared__ char smem[];
    float* sPat = (float*)smem;
    const uint32_t sb = smem_u32(smem);
    const int tid = threadIdx.x, lane = tid & 31, wid = tid >> 5;
    const int wm = wid >> 2, wn = wid & 3;
    const int p0 = blockIdx.x * PPB;

    auto stage = [&](int c){
        const uint32_t aB = sb + SM_B + (c&1)*16384;
        const int kk = c*KCH;
        #pragma unroll
        for (int i=0;i<4;i++){
            int lin = tid + i*256;
            int k = lin >> 4, nq = lin & 15;
            cpa16(aB + k*256 + ((nq ^ (k & 7)) << 4), g_Bh + (kk+k)*DIM + nq*8);
        }
    };

    stage(0); cpa_commit();

    // pattern: direct LDG (overlaps with stage(0) transfer)
    {
        const float isq = 0.17677669529663687f;
        int pp = tid >> 3, h = (tid >> 1) & 3, qi = tid & 1;
        int pr = min(p0 + pp, NPAIR-1);
        int aa = pr / PV, bb = pr % PV;
        int ca0 = 2*aa, cb0 = 2*bb + 1;
        int cq = qi ? cb0 : ca0;
        const float* q  = g_qk + (0*NCOMBO + cq )*DIM + h*DHD;
        const float* k0 = g_qk + (1*NCOMBO + ca0)*DIM + h*DHD;
        const float* k1 = g_qk + (1*NCOMBO + cb0)*DIM + h*DHD;
        float s0=0.f, s1=0.f;
        #pragma unroll
        for (int i=0;i<DHD;i++){ float qv = q[i]; s0 += qv*k0[i]; s1 += qv*k1[i]; }
        s0 *= isq; s1 *= isq;
        float m = fmaxf(s0, s1);
        float e0 = __expf(s0-m), e1 = __expf(s1-m);
        float p = e0/(e0+e1);
        sPat[pp*16 + h*4 + qi*2 + 0] = 0.5f + 0.5f*p;
        sPat[pp*16 + h*4 + qi*2 + 1] = 0.5f + 0.5f*(1.0f-p);
    }
    cpa_wait0();
    __syncthreads();

    // A-compute state: thread = (row = tid>>2 of 64, q16 = tid&3); direct-LDG Acz
    const int row = tid >> 2, q16 = tid & 3;
    const int lp = row >> 1, qi = row & 1;
    const int pairT = min(p0 + lp, NPAIR-1);
    const __half* gzA = g_Acz + (size_t)(2*(pairT / PV))*320;
    const __half* gzB = g_Acz + (size_t)(2*(pairT % PV) + 1)*320;
    float wza[5], wzb[5];
    wza[0] = qi ? 0.f : 1.f;  wzb[0] = qi ? 1.f : 0.f;
    #pragma unroll
    for (int h=0; h<NH; h++){
        wza[1+h] = sPat[lp*16 + h*4 + qi*2 + 0];
        wzb[1+h] = sPat[lp*16 + h*4 + qi*2 + 1];
    }

    float acc[2][4][4];
    #pragma unroll
    for (int i=0;i<2;i++)
        #pragma unroll
        for (int j=0;j<4;j++)
            #pragma unroll
            for (int k=0;k<4;k++) acc[i][j][k] = 0.f;

    for (int c = 0; c < NCHUNK; c++){
        const __half* pa = gzA + (size_t)c*(NCOMBOP*320);
        const __half* pb = gzB + (size_t)c*(NCOMBOP*320);
        #pragma unroll
        for (int g=0; g<2; g++){
            const int colo = q16*16 + g*8;       // half offset within 64-col slot row
            float pr8[8] = {0,0,0,0,0,0,0,0};
            #pragma unroll
            for (int s=0; s<5; s++){
                uint4 va = *(const uint4*)(pa + s*64 + colo);
                uint4 vb = *(const uint4*)(pb + s*64 + colo);
                float2 a0 = __half22float2(*(__half2*)&va.x);
                float2 a1 = __half22float2(*(__half2*)&va.y);
                float2 a2 = __half22float2(*(__half2*)&va.z);
                float2 a3 = __half22float2(*(__half2*)&va.w);
                float2 b0 = __half22float2(*(__half2*)&vb.x);
                float2 b1 = __half22float2(*(__half2*)&vb.y);
                float2 b2 = __half22float2(*(__half2*)&vb.z);
                float2 b3 = __half22float2(*(__half2*)&vb.w);
                float wa = wza[s], wb = wzb[s];
                pr8[0] += wa*a0.x + wb*b0.x;  pr8[1] += wa*a0.y + wb*b0.y;
                pr8[2] += wa*a1.x + wb*b1.x;  pr8[3] += wa*a1.y + wb*b1.y;
                pr8[4] += wa*a2.x + wb*b2.x;  pr8[5] += wa*a2.y + wb*b2.y;
                pr8[6] += wa*a3.x + wb*b3.x;  pr8[7] += wa*a3.y + wb*b3.y;
            }
            __half2 h0 = __floats2half2_rn(fmaxf(pr8[0],0.f), fmaxf(pr8[1],0.f));
            __half2 h1 = __floats2half2_rn(fmaxf(pr8[2],0.f), fmaxf(pr8[3],0.f));
            __half2 h2 = __floats2half2_rn(fmaxf(pr8[4],0.f), fmaxf(pr8[5],0.f));
            __half2 h3 = __floats2half2_rn(fmaxf(pr8[6],0.f), fmaxf(pr8[7],0.f));
            int kq = q16*2 + g;
            uint32_t off = (uint32_t)(SM_ATILE + row*128 + ((kq ^ permA(row)) << 4));
            uint4 pk; pk.x = *(uint32_t*)&h0; pk.y = *(uint32_t*)&h1;
                      pk.z = *(uint32_t*)&h2; pk.w = *(uint32_t*)&h3;
            *(uint4*)(smem + off) = pk;
        }
        __syncthreads();

        if (c + 1 < NCHUNK){ stage(c + 1); cpa_commit(); }

        {
            const uint32_t aA = sb + SM_ATILE;
            const uint32_t aB = sb + SM_B + (c&1)*16384;
            #pragma unroll
            for (int ks=0; ks<4; ks++){
                uint32_t ah[2][4];
                #pragma unroll
                for (int mf=0; mf<2; mf++){
                    int r  = wm*32 + mf*16 + (lane & 15);
                    int kq = ks*2 + (lane >> 4);
                    ldsm4(ah[mf], aA + r*128 + ((kq ^ permA(r)) << 4));
                }
                int kr = ks*16 + (lane & 15);
                #pragma unroll
                for (int nb=0; nb<2; nb++){
                    int nq = wn*4 + nb*2 + (lane >> 4);
                    uint32_t bh[4];
                    ldsm4t(bh, aB + kr*256 + ((nq ^ (kr & 7)) << 4));
                    #pragma unroll
                    for (int mf=0; mf<2; mf++){
                        mma16816(acc[mf][nb*2],   ah[mf], bh[0], bh[1]);
                        mma16816(acc[mf][nb*2+1], ah[mf], bh[2], bh[3]);
                    }
                }
            }
        }
        if (c + 1 < NCHUNK) cpa_wait0();
        __syncthreads();
    }

    // epilogue: direct LDG base + acc -> g_table
    #pragma unroll
    for (int mf=0; mf<2; mf++){
        #pragma unroll
        for (int hh=0; hh<2; hh++){
            int r = wm*32 + mf*16 + (lane >> 2) + hh*8;
            int rlp = r >> 1, rqi = r & 1;
            int pair = p0 + rlp;
            int cpair = min(pair, NPAIR-1);
            int ra = cpair / PV, rb = cpair % PV;
            int rca = 2*ra, rcb = 2*rb + 1;
            int cq = rqi ? rcb : rca;
            int gm = pair*2 + rqi;
            float wA[4], wB[4];
            #pragma unroll
            for (int h=0; h<NH; h++){
                wA[h] = sPat[rlp*16 + h*4 + rqi*2 + 0];
                wB[h] = sPat[rlp*16 + h*4 + rqi*2 + 1];
            }
            const float*  eu  = g_EU  + cq*PVP;
            const __half* aua = g_AUh + (rca*NH)*PVP;
            const __half* aub = g_AUh + (rcb*NH)*PVP;
            #pragma unroll
            for (int nf=0; nf<4; nf++){
                int n = wn*32 + nf*8 + (lane & 3)*2;
                float2 base = *(const float2*)(eu + n);
                #pragma unroll
                for (int h=0; h<NH; h++){
                    float2 fa = __half22float2(*(const __half2*)(aua + h*PVP + n));
                    float2 fb = __half22float2(*(const __half2*)(aub + h*PVP + n));
                    base.x += wA[h]*fa.x + wB[h]*fb.x;
                    base.y += wA[h]*fa.y + wB[h]*fb.y;
                }
                if (pair < NPAIR){
                    float* ts = g_table + (size_t)gm*PV;
                    float c0 = acc[mf][nf][hh*2+0] + base.x;
                    float c1 = acc[mf][nf][hh*2+1] + base.y;
                    if (n   < PV) ts[n]   = c0;
                    if (n+1 < PV) ts[n+1] = c1;
                }
            }
        }
    }
}

// ---------------- G: gather, 4 examples/warp (proven) ----------------
__global__ void kG(const int* __restrict__ x, float* __restrict__ out, int B){
    int e0 = (blockIdx.x*8 + (threadIdx.x >> 5))*4;
    int lane = threadIdx.x & 31;
    if (e0 >= B) return;

    const float2* src[4];
    float2* dst[4];
    bool has[4];
    #pragma unroll
    for (int e=0;e<4;e++){
        int ex = e0 + e;
        has[e] = ex < B;
        int cx = has[e] ? ex : e0;
        int a = x[cx*2], b = x[cx*2+1];
        src[e] = (const float2*)(g_table + (size_t)(a*PV + b)*226);
        dst[e] = (float2*)(out + (size_t)cx*226);
    }

    float2 v[4][4];
    #pragma unroll
    for (int e=0;e<4;e++)
        #pragma unroll
        for (int i=0;i<4;i++){
            int idx = lane + i*32;
            if (idx < PV) v[e][i] = src[e][idx];
        }
    #pragma unroll
    for (int e=0;e<4;e++){
        if (!has[e]) continue;
        #pragma unroll
        for (int i=0;i<4;i++){
            int idx = lane + i*32;
            if (idx < PV) dst[e][idx] = v[e][i];
        }
    }
}

// ---------------- launch ----------------
extern "C" void kernel_launch(void* const* d_in, const int* in_sizes, int n_in,
                              void* d_out, int out_size){
    const int*   x   = (const int*)  d_in[0];
    const float* tok = (const float*)d_in[1];
    const float* pos = (const float*)d_in[2];
    const float* WQ  = (const float*)d_in[3];
    const float* WK  = (const float*)d_in[4];
    const float* WV  = (const float*)d_in[5];
    const float* WO  = (const float*)d_in[6];
    const float* W1  = (const float*)d_in[7];
    const float* b1  = (const float*)d_in[8];
    const float* W2  = (const float*)d_in[9];
    const float* b2  = (const float*)d_in[10];
    const float* WU  = (const float*)d_in[11];
    float* out = (float*)d_out;
    const int B = in_sizes[0] / 2;

    cudaFuncSetAttribute(kFB9, cudaFuncAttributeMaxDynamicSharedMemorySize, SMEM_TOT);

    kP1<<<100, 256>>>(tok, pos, WO, W1, WQ, WK, WV, b1, W2, WU, b2);
    kP2<<<160, 256>>>();
    kFB9<<<GEMM_GRID, 256, SMEM_TOT>>>();
    kG<<<(B + 31)/32, 256>>>(x, out, B);
}

// round 16
// speedup vs baseline: 1.2295x; 1.2295x over previous
#include <cuda_runtime.h>
#include <cuda_fp16.h>
#include <cstdint>

#define PV   113
#define PVP  128
#define DIM  128
#define NH   4
#define DHD  32
#define HID  512
#define NCOMBO 226
#define NCOMBOP 228
#define NPAIR (PV*PV)      // 12769
#define NTOK  (NPAIR*2)    // 25538
#define PPB   32           // pairs per CTA (64 rows)
#define KCH   64
#define NCHUNK 8
#define GEMM_GRID ((NPAIR + PPB - 1)/PPB)   // 400

// ---------------- device scratch (zero-initialized) ----------------
__device__ __align__(16) float g_vv [256*DIM];
__device__ __align__(16) float g_OW1[DIM*HID];
__device__ __align__(16) float g_OU [DIM*PV];
__device__ __align__(16) float g_qk [2*NCOMBO*DIM + 4*DIM];
__device__ __align__(16) float g_EU [NCOMBOP*PVP];              // fp32 (b2 folded)
__device__ __align__(16) __half g_AUh[NCOMBOP*NH*PVP];          // fp16
__device__ __align__(16) __half g_Acz[NCHUNK*NCOMBOP*5*64];     // [chunk][combo][slot0=E,1..4=A][64]
__device__ __align__(16) __half g_Bh[HID*DIM];                  // [k][n] W2U fp16
__device__ __align__(16) float g_table[(size_t)NTOK*PV];

// ---------------- helpers ----------------
__device__ __forceinline__ uint32_t smem_u32(const void* p){
    uint32_t a;
    asm("{ .reg .u64 t; cvta.to.shared.u64 t, %1; cvt.u32.u64 %0, t; }" : "=r"(a) : "l"(p));
    return a;
}
__device__ __forceinline__ void cpa16(uint32_t dst, const void* src){
    asm volatile("cp.async.cg.shared.global [%0], [%1], 16;" :: "r"(dst), "l"(src));
}
__device__ __forceinline__ void cpa_commit(){ asm volatile("cp.async.commit_group;"); }
__device__ __forceinline__ void cpa_wait0(){ asm volatile("cp.async.wait_group 0;"); }
__device__ __forceinline__ void ldsm4(uint32_t* r, uint32_t a){
    asm volatile("ldmatrix.sync.aligned.m8n8.x4.shared.b16 {%0,%1,%2,%3}, [%4];"
        : "=r"(r[0]),"=r"(r[1]),"=r"(r[2]),"=r"(r[3]) : "r"(a));
}
__device__ __forceinline__ void ldsm4t(uint32_t* r, uint32_t a){
    asm volatile("ldmatrix.sync.aligned.m8n8.x4.trans.shared.b16 {%0,%1,%2,%3}, [%4];"
        : "=r"(r[0]),"=r"(r[1]),"=r"(r[2]),"=r"(r[3]) : "r"(a));
}
__device__ __forceinline__ void mma16816(float* c, const uint32_t* a, uint32_t b0, uint32_t b1){
    asm volatile("mma.sync.aligned.m16n8k16.row.col.f32.f16.f16.f32 "
        "{%0,%1,%2,%3}, {%4,%5,%6,%7}, {%8,%9}, {%0,%1,%2,%3};"
        : "+f"(c[0]),"+f"(c[1]),"+f"(c[2]),"+f"(c[3])
        : "r"(a[0]),"r"(a[1]),"r"(a[2]),"r"(a[3]), "r"(b0),"r"(b1));
}
__device__ __forceinline__ int permA(int m){ int t = m & 7; return (t>>1) | ((t&1)<<2); }

// ---------------- tiled 64x64 GEMM core (K multiple of 32) ----------------
template<class LA, class LB, class LC>
__device__ __forceinline__ void tg64(float (&As)[32][68], float (&Bs)[32][68],
                                     int K, LA la, LB lb, LC lc){
    const int tid = threadIdx.x;
    const int tx = tid & 15, ty = tid >> 4;
    float acc[4][4] = {};
    for (int k0 = 0; k0 < K; k0 += 32){
        {
            int am = tid >> 2, ak = (tid & 3) * 8;
            #pragma unroll
            for (int u=0;u<8;u++) As[ak+u][am] = la(am, k0+ak+u);
        }
        {
            int bk = tid >> 3, bn = (tid & 7) * 8;
            #pragma unroll
            for (int u=0;u<8;u++) Bs[bk][bn+u] = lb(k0+bk, bn+u);
        }
        __syncthreads();
        #pragma unroll
        for (int k=0;k<32;k++){
            float4 a4 = *(const float4*)&As[k][ty*4];
            float4 b4 = *(const float4*)&Bs[k][tx*4];
            float av[4] = {a4.x,a4.y,a4.z,a4.w};
            float bv[4] = {b4.x,b4.y,b4.z,b4.w};
            #pragma unroll
            for (int i=0;i<4;i++)
                #pragma unroll
                for (int j=0;j<4;j++) acc[i][j] += av[i]*bv[j];
        }
        __syncthreads();
    }
    #pragma unroll
    for (int i=0;i<4;i++)
        #pragma unroll
        for (int j=0;j<4;j++) lc(ty*4+i, tx*4+j, acc[i][j]);
}

// ---------------- P1: weight folds + E-side GEMMs ----------------
__global__ void __launch_bounds__(256) kP1(
    const float* __restrict__ tok_emb, const float* __restrict__ pos_emb,
    const float* __restrict__ WO, const float* __restrict__ W1,
    const float* __restrict__ WQ, const float* __restrict__ WK,
    const float* __restrict__ WV, const float* __restrict__ b1,
    const float* __restrict__ W2, const float* __restrict__ WU,
    const float* __restrict__ b2){
    __shared__ float As[32][68], Bs[32][68];
    int b = blockIdx.x;
    if (b < 16){                                  // OW1 = WO @ W1
        int l = b; int m0 = (l>>3)*64, n0 = (l&7)*64;
        tg64(As, Bs, 128,
            [&](int m,int k){ return WO[(m0+m)*DIM + k]; },
            [&](int k,int n){ return W1[k*HID + n0+n]; },
            [&](int m,int n,float v){ g_OW1[(m0+m)*HID + n0+n] = v; });
    } else if (b < 20){                           // OU = WO @ WU^T
        int l = b-16; int m0 = (l>>1)*64, n0 = (l&1)*64;
        tg64(As, Bs, 128,
            [&](int m,int k){ return WO[(m0+m)*DIM + k]; },
            [&](int k,int n){ int nn=n0+n; return nn<PV ? WU[nn*DIM + k] : 0.f; },
            [&](int m,int n,float v){ int nn=n0+n; if (nn<PV) g_OU[(m0+m)*PV + nn] = v; });
    } else if (b < 36){                           // Bh = fp16(W2 @ WU^T)
        int l = b-20; int m0 = (l>>1)*64, n0 = (l&1)*64;
        tg64(As, Bs, 128,
            [&](int m,int k){ return W2[(m0+m)*DIM + k]; },
            [&](int k,int n){ int nn=n0+n; return nn<PV ? WU[nn*DIM + k] : 0.f; },
            [&](int m,int n,float v){ g_Bh[(m0+m)*DIM + n0+n] = __float2half_rn(v); });
    } else if (b < 52){                           // q/k = E @ WQ/WK
        int l = b-36; int sel = l >> 3; l &= 7;
        int m0 = (l>>1)*64, n0 = (l&1)*64;
        const float* W = sel ? WK : WQ;
        tg64(As, Bs, 128,
            [&](int m,int k){ int c=m0+m; return c<NCOMBO ?
                tok_emb[(c>>1)*DIM + k] + pos_emb[(c&1)*DIM + k] : 0.f; },
            [&](int k,int n){ int nn=n0+n; return W[(nn>>5)*(DIM*DHD) + k*DHD + (nn&31)]; },
            [&](int m,int n,float v){ int c=m0+m; if (c<NCOMBO)
                g_qk[(sel*NCOMBO + c)*DIM + n0+n] = v; });
    } else if (b < 60){                           // vv = E @ WV
        int l = b-52; int m0 = (l>>1)*64, n0 = (l&1)*64;
        tg64(As, Bs, 128,
            [&](int m,int k){ int c=m0+m; return c<NCOMBO ?
                tok_emb[(c>>1)*DIM + k] + pos_emb[(c&1)*DIM + k] : 0.f; },
            [&](int k,int n){ int nn=n0+n; return WV[(nn>>5)*(DIM*DHD) + k*DHD + (nn&31)]; },
            [&](int m,int n,float v){ g_vv[(m0+m)*DIM + n0+n] = v; });
    } else if (b < 92){                           // EW1 = E @ W1 + b1 -> Acz slot 0
        int l = b-60; int m0 = (l>>3)*64, n0 = (l&7)*64;
        tg64(As, Bs, 128,
            [&](int m,int k){ int c=m0+m; return c<NCOMBO ?
                tok_emb[(c>>1)*DIM + k] + pos_emb[(c&1)*DIM + k] : 0.f; },
            [&](int k,int n){ return W1[k*HID + n0+n]; },
            [&](int m,int n,float v){ int c=m0+m, j=n0+n; if (c<NCOMBO)
                g_Acz[(((j>>6)*NCOMBOP + c)*5 + 0)*64 + (j&63)] = __float2half_rn(v + b1[j]); });
    } else {                                      // EU = (E + b2) @ WU^T (fp32)
        int l = b-92; int m0 = (l>>1)*64, n0 = (l&1)*64;
        tg64(As, Bs, 128,
            [&](int m,int k){ int c=m0+m; return (c<NCOMBO ?
                tok_emb[(c>>1)*DIM + k] + pos_emb[(c&1)*DIM + k] : 0.f) + b2[k]; },
            [&](int k,int n){ int nn=n0+n; return nn<PV ? WU[nn*DIM + k] : 0.f; },
            [&](int m,int n,float v){ int c=m0+m; if (c<NCOMBO)
                g_EU[c*PVP + n0+n] = v; });
    }
}

// ---------------- P2: vv-dependent folds (merged) ----------------
__global__ void __launch_bounds__(256) kP2(){
    __shared__ float As[32][68], Bs[32][68];
    int b = blockIdx.x;
    if (b < 128){                                 // AW1[h] = vv_h @ OW1_h -> Acz slots 1..4
        int h = b >> 5; int l = b & 31;
        int m0 = (l>>3)*64, n0 = (l&7)*64;
        tg64(As, Bs, 32,
            [&](int m,int k){ return g_vv[(m0+m)*DIM + h*DHD + k]; },
            [&](int k,int n){ return g_OW1[(h*DHD + k)*HID + n0+n]; },
            [&](int m,int n,float v){ int c=m0+m, j=n0+n; if (c<NCOMBO)
                g_Acz[(((j>>6)*NCOMBOP + c)*5 + 1 + h)*64 + (j&63)] = __float2half_rn(v); });
    } else {                                      // AU[h] = vv_h @ OU_h (fp16)
        int l = b-128; int h = l >> 3; int t = l & 7;
        int m0 = (t>>1)*64, n0 = (t&1)*64;
        tg64(As, Bs, 32,
            [&](int m,int k){ return g_vv[(m0+m)*DIM + h*DHD + k]; },
            [&](int k,int n){ int nn=n0+n; return nn<PV ? g_OU[(h*DHD + k)*PV + nn] : 0.f; },
            [&](int m,int n,float v){ int c=m0+m, nn=n0+n; if (c<NCOMBO && nn<PV)
                g_AUh[(c*NH + h)*PVP + nn] = __float2half_rn(v); });
    }
}

// ---------------- kFB8: R12 structure + early B staging ----------------
#define SM_PAT   0        // 2048
#define SM_CMB   2048     // 256
#define SM_ATILE 2560     // 8192
#define SM_ACZ   10752    // 34*656 = 22304
#define SM_B     33280    // 2*16384
#define SMEM_TOT 66048
#define ACZ_STR  656

__global__ void __launch_bounds__(256, 3) kFB8(){
    extern __shared__ char smem[];
    float* sPat = (float*)smem;
    int*   sCmb = (int*)(smem + SM_CMB);
    const uint32_t sb = smem_u32(smem);
    const int tid = threadIdx.x, lane = tid & 31, wid = tid >> 5;
    const int wm = wid >> 2, wn = wid & 3;
    const int p0 = blockIdx.x * PPB;
    const int a0g = p0 / PV;

    if (tid < 32) {
        int pr = min(p0 + tid, NPAIR-1);
        sCmb[tid] = 2*(pr % PV) + 1;
    } else if (tid == 32) sCmb[32] = 2*a0g;
    else if (tid == 33)   sCmb[33] = 2*(min(p0 + PPB - 1, NPAIR-1)/PV);
    __syncthreads();

    auto stageZ = [&](int c){
        const uint32_t aZ = sb + SM_ACZ;
        for (int i=0;i<6;i++){
            int lin = tid + i*256;
            if (lin < 1360){
                int row = lin / 40, x = lin % 40;
                cpa16(aZ + row*ACZ_STR + x*16,
                      g_Acz + ((size_t)(c*NCOMBOP + sCmb[row]))*320 + x*8);
            }
        }
    };
    auto stageB = [&](int c){
        const uint32_t aB = sb + SM_B + (c&1)*16384;
        const int kk = c*KCH;
        #pragma unroll
        for (int i=0;i<4;i++){
            int lin = tid + i*256;
            int k = lin >> 4, nq = lin & 15;
            cpa16(aB + k*256 + ((nq ^ (k & 7)) << 4), g_Bh + (kk+k)*DIM + nq*8);
        }
    };

    stageZ(0); stageB(0); cpa_commit();

    // pattern: direct LDG (overlaps with stage(0) transfer)
    {
        const float isq = 0.17677669529663687f;
        int pp = tid >> 3, h = (tid >> 1) & 3, qi = tid & 1;
        int pr = min(p0 + pp, NPAIR-1);
        int aa = pr / PV, bb = pr % PV;
        int ca0 = 2*aa, cb0 = 2*bb + 1;
        int cq = qi ? cb0 : ca0;
        const float* q  = g_qk + (0*NCOMBO + cq )*DIM + h*DHD;
        const float* k0 = g_qk + (1*NCOMBO + ca0)*DIM + h*DHD;
        const float* k1 = g_qk + (1*NCOMBO + cb0)*DIM + h*DHD;
        float s0=0.f, s1=0.f;
        #pragma unroll
        for (int i=0;i<DHD;i++){ float qv = q[i]; s0 += qv*k0[i]; s1 += qv*k1[i]; }
        s0 *= isq; s1 *= isq;
        float m = fmaxf(s0, s1);
        float e0 = __expf(s0-m), e1 = __expf(s1-m);
        float p = e0/(e0+e1);
        sPat[pp*16 + h*4 + qi*2 + 0] = 0.5f + 0.5f*p;
        sPat[pp*16 + h*4 + qi*2 + 1] = 0.5f + 0.5f*(1.0f-p);
    }
    cpa_wait0();
    __syncthreads();

    const int row = tid >> 2, q16 = tid & 3;
    const int lp = row >> 1, qi = row & 1;
    const int asel = (min(p0 + lp, NPAIR-1)/PV != a0g) ? 1 : 0;
    const uint32_t zb = sb + SM_ACZ + lp*ACZ_STR;
    const uint32_t za = sb + SM_ACZ + (32 + asel)*ACZ_STR;
    float wza[5], wzb[5];
    wza[0] = qi ? 0.f : 1.f;  wzb[0] = qi ? 1.f : 0.f;
    #pragma unroll
    for (int h=0; h<NH; h++){
        wza[1+h] = sPat[lp*16 + h*4 + qi*2 + 0];
        wzb[1+h] = sPat[lp*16 + h*4 + qi*2 + 1];
    }

    float acc[2][4][4];
    #pragma unroll
    for (int i=0;i<2;i++)
        #pragma unroll
        for (int j=0;j<4;j++)
            #pragma unroll
            for (int k=0;k<4;k++) acc[i][j][k] = 0.f;

    for (int c = 0; c < NCHUNK; c++){
        // B(c+1) staged early: hazard-free (double-buffered), overlaps A-compute
        if (c + 1 < NCHUNK) stageB(c + 1);

        #pragma unroll
        for (int g=0; g<2; g++){
            const int boff = q16*32 + g*16;
            float pr8[8] = {0,0,0,0,0,0,0,0};
            #pragma unroll
            for (int s=0; s<5; s++){
                uint4 va = *(const uint4*)(smem + (za - sb) + s*128 + boff);
                uint4 vb = *(const uint4*)(smem + (zb - sb) + s*128 + boff);
                float2 a0 = __half22float2(*(__half2*)&va.x);
                float2 a1 = __half22float2(*(__half2*)&va.y);
                float2 a2 = __half22float2(*(__half2*)&va.z);
                float2 a3 = __half22float2(*(__half2*)&va.w);
                float2 b0 = __half22float2(*(__half2*)&vb.x);
                float2 b1 = __half22float2(*(__half2*)&vb.y);
                float2 b2 = __half22float2(*(__half2*)&vb.z);
                float2 b3 = __half22float2(*(__half2*)&vb.w);
                float wa = wza[s], wb = wzb[s];
                pr8[0] += wa*a0.x + wb*b0.x;  pr8[1] += wa*a0.y + wb*b0.y;
                pr8[2] += wa*a1.x + wb*b1.x;  pr8[3] += wa*a1.y + wb*b1.y;
                pr8[4] += wa*a2.x + wb*b2.x;  pr8[5] += wa*a2.y + wb*b2.y;
                pr8[6] += wa*a3.x + wb*b3.x;  pr8[7] += wa*a3.y + wb*b3.y;
            }
            __half2 h0 = __floats2half2_rn(fmaxf(pr8[0],0.f), fmaxf(pr8[1],0.f));
            __half2 h1 = __floats2half2_rn(fmaxf(pr8[2],0.f), fmaxf(pr8[3],0.f));
            __half2 h2 = __floats2half2_rn(fmaxf(pr8[4],0.f), fmaxf(pr8[5],0.f));
            __half2 h3 = __floats2half2_rn(fmaxf(pr8[6],0.f), fmaxf(pr8[7],0.f));
            int kq = q16*2 + g;
            uint32_t off = (uint32_t)(SM_ATILE + row*128 + ((kq ^ permA(row)) << 4));
            uint4 pk; pk.x = *(uint32_t*)&h0; pk.y = *(uint32_t*)&h1;
                      pk.z = *(uint32_t*)&h2; pk.w = *(uint32_t*)&h3;
            *(uint4*)(smem + off) = pk;
        }
        __syncthreads();     // Atile ready; ACZ(c) fully consumed

        if (c + 1 < NCHUNK){ stageZ(c + 1); cpa_commit(); }

        {
            const uint32_t aA = sb + SM_ATILE;
            const uint32_t aB = sb + SM_B + (c&1)*16384;
            #pragma unroll
            for (int ks=0; ks<4; ks++){
                uint32_t ah[2][4];
                #pragma unroll
                for (int mf=0; mf<2; mf++){
                    int r  = wm*32 + mf*16 + (lane & 15);
                    int kq = ks*2 + (lane >> 4);
                    ldsm4(ah[mf], aA + r*128 + ((kq ^ permA(r)) << 4));
                }
                int kr = ks*16 + (lane & 15);
                #pragma unroll
                for (int nb=0; nb<2; nb++){
                    int nq = wn*4 + nb*2 + (lane >> 4);
                    uint32_t bh[4];
                    ldsm4t(bh, aB + kr*256 + ((nq ^ (kr & 7)) << 4));
                    #pragma unroll
                    for (int mf=0; mf<2; mf++){
                        mma16816(acc[mf][nb*2],   ah[mf], bh[0], bh[1]);
                        mma16816(acc[mf][nb*2+1], ah[mf], bh[2], bh[3]);
                    }
                }
            }
        }
        if (c + 1 < NCHUNK) cpa_wait0();
        __syncthreads();
    }

    // epilogue: direct LDG base + acc -> g_table
    #pragma unroll
    for (int mf=0; mf<2; mf++){
        #pragma unroll
        for (int hh=0; hh<2; hh++){
            int r = wm*32 + mf*16 + (lane >> 2) + hh*8;
            int rlp = r >> 1, rqi = r & 1;
            int pair = p0 + rlp;
            int cpair = min(pair, NPAIR-1);
            int ra = cpair / PV, rb = cpair % PV;
            int rca = 2*ra, rcb = 2*rb + 1;
            int cq = rqi ? rcb : rca;
            int gm = pair*2 + rqi;
            float wA[4], wB[4];
            #pragma unroll
            for (int h=0; h<NH; h++){
                wA[h] = sPat[rlp*16 + h*4 + rqi*2 + 0];
                wB[h] = sPat[rlp*16 + h*4 + rqi*2 + 1];
            }
            const float*  eu  = g_EU  + cq*PVP;
            const __half* aua = g_AUh + (rca*NH)*PVP;
            const __half* aub = g_AUh + (rcb*NH)*PVP;
            #pragma unroll
            for (int nf=0; nf<4; nf++){
                int n = wn*32 + nf*8 + (lane & 3)*2;
                float2 base = *(const float2*)(eu + n);
                #pragma unroll
                for (int h=0; h<NH; h++){
                    float2 fa = __half22float2(*(const __half2*)(aua + h*PVP + n));
                    float2 fb = __half22float2(*(const __half2*)(aub + h*PVP + n));
                    base.x += wA[h]*fa.x + wB[h]*fb.x;
                    base.y += wA[h]*fa.y + wB[h]*fb.y;
                }
                if (pair < NPAIR){
                    float* ts = g_table + (size_t)gm*PV;
                    float c0 = acc[mf][nf][hh*2+0] + base.x;
                    float c1 = acc[mf][nf][hh*2+1] + base.y;
                    if (n   < PV) ts[n]   = c0;
                    if (n+1 < PV) ts[n+1] = c1;
                }
            }
        }
    }
}

// ---------------- G: gather, 4 examples/warp (proven) ----------------
__global__ void kG(const int* __restrict__ x, float* __restrict__ out, int B){
    int e0 = (blockIdx.x*8 + (threadIdx.x >> 5))*4;
    int lane = threadIdx.x & 31;
    if (e0 >= B) return;

    const float2* src[4];
    float2* dst[4];
    bool has[4];
    #pragma unroll
    for (int e=0;e<4;e++){
        int ex = e0 + e;
        has[e] = ex < B;
        int cx = has[e] ? ex : e0;
        int a = x[cx*2], b = x[cx*2+1];
        src[e] = (const float2*)(g_table + (size_t)(a*PV + b)*226);
        dst[e] = (float2*)(out + (size_t)cx*226);
    }

    float2 v[4][4];
    #pragma unroll
    for (int e=0;e<4;e++)
        #pragma unroll
        for (int i=0;i<4;i++){
            int idx = lane + i*32;
            if (idx < PV) v[e][i] = src[e][idx];
        }
    #pragma unroll
    for (int e=0;e<4;e++){
        if (!has[e]) continue;
        #pragma unroll
        for (int i=0;i<4;i++){
            int idx = lane + i*32;
            if (idx < PV) dst[e][idx] = v[e][i];
        }
    }
}

// ---------------- launch ----------------
extern "C" void kernel_launch(void* const* d_in, const int* in_sizes, int n_in,
                              void* d_out, int out_size){
    const int*   x   = (const int*)  d_in[0];
    const float* tok = (const float*)d_in[1];
    const float* pos = (const float*)d_in[2];
    const float* WQ  = (const float*)d_in[3];
    const float* WK  = (const float*)d_in[4];
    const float* WV  = (const float*)d_in[5];
    const float* WO  = (const float*)d_in[6];
    const float* W1  = (const float*)d_in[7];
    const float* b1  = (const float*)d_in[8];
    const float* W2  = (const float*)d_in[9];
    const float* b2  = (const float*)d_in[10];
    const float* WU  = (const float*)d_in[11];
    float* out = (float*)d_out;
    const int B = in_sizes[0] / 2;

    cudaFuncSetAttribute(kFB8, cudaFuncAttributeMaxDynamicSharedMemorySize, SMEM_TOT);

    kP1<<<100, 256>>>(tok, pos, WO, W1, WQ, WK, WV, b1, W2, WU, b2);
    kP2<<<160, 256>>>();
    kFB8<<<GEMM_GRID, 256, SMEM_TOT>>>();
    kG<<<(B + 31)/32, 256>>>(x, out, B);
}